// round 16
// baseline (speedup 1.0000x reference)
#include <cuda_runtime.h>
#include <math.h>

#define N_NODES 5000
#define DEG 16
#define S 17
#define T 10
#define MN 10
#define D 128
#define EPS 0.1f
#define N_OUTER 3
#define N_SINK 5
#define TM 100
#define NPB 10
#define LOG2E 1.4426950408889634f
#define LN2 0.6931471805599453f
#define FULLMASK 0xffffffffu

__device__ __forceinline__ float ex2(float x) {
    float r; asm("ex2.approx.ftz.f32 %0, %1;" : "=f"(r) : "f"(x)); return r;
}

// ---------------- device-global precomputed state / scratch ----------------
__device__ float g_alpha;
__device__ float g_C2[T*MN*MN];
__device__ float g_q[T*MN];
__device__ float g_hC2[T*MN];
__device__ float g_Hq[T*MN];
__device__ float g_f2sq[T*MN];
__device__ float g_Pm[(size_t)N_NODES * TM];   // -2<x_n,F2_tm>
__device__ float g_xsq[N_NODES];

// ---------------- kernel 1: Pm GEMM + fused precompute (block 0) ----------
// NPB=10 / 256 threads -> 500 blocks: better SM coverage for the
// latency-bound GEMM (was 250 blocks at NPB=20/512).
__global__ __launch_bounds__(256) void pm_pre_kernel(const float* __restrict__ x,
                                                     const float* __restrict__ tf,
                                                     const float* __restrict__ tmpl,
                                                     const float* __restrict__ q0,
                                                     const float* __restrict__ alpha0) {
    __shared__ __align__(16) float4 sx4[NPB][D/4 + 1];
    int base = blockIdx.x * NPB;
    int tid = threadIdx.x;

    for (int idx = tid; idx < NPB*(D/4); idx += 256) {
        int r = idx / (D/4), c = idx % (D/4);
        sx4[r][c] = ((const float4*)(x + (size_t)(base + r)*D))[c];
    }
    __syncthreads();
    if (tid < NPB) {
        float s = 0.f;
        #pragma unroll 8
        for (int d = 0; d < D/4; d++) {
            float4 v = sx4[tid][d];
            s += v.x*v.x + v.y*v.y + v.z*v.z + v.w*v.w;
        }
        g_xsq[base + tid] = s;
    }
    if (tid < NPB * (TM/4)) {
        int nl = tid % NPB, tm0 = (tid / NPB) * 4;
        const float4* b0 = (const float4*)(tf + (size_t)(tm0+0)*D);
        const float4* b1 = (const float4*)(tf + (size_t)(tm0+1)*D);
        const float4* b2 = (const float4*)(tf + (size_t)(tm0+2)*D);
        const float4* b3 = (const float4*)(tf + (size_t)(tm0+3)*D);
        float a0=0.f, a1=0.f, a2=0.f, a3=0.f;
        #pragma unroll 8
        for (int d = 0; d < D/4; d++) {
            float4 av = sx4[nl][d];
            float4 r0 = b0[d], r1 = b1[d], r2 = b2[d], r3 = b3[d];
            a0 += av.x*r0.x + av.y*r0.y + av.z*r0.z + av.w*r0.w;
            a1 += av.x*r1.x + av.y*r1.y + av.z*r1.z + av.w*r1.w;
            a2 += av.x*r2.x + av.y*r2.y + av.z*r2.z + av.w*r2.w;
            a3 += av.x*r3.x + av.y*r3.y + av.z*r3.z + av.w*r3.w;
        }
        size_t o = (size_t)(base + nl)*TM + tm0;
        g_Pm[o+0] = -2.f*a0; g_Pm[o+1] = -2.f*a1;
        g_Pm[o+2] = -2.f*a2; g_Pm[o+3] = -2.f*a3;
    }

    if (blockIdx.x == 0) {
        if (tid == 0) g_alpha = 1.0f / (1.0f + expf(-alpha0[0]));
        if (tid < T) {
            float mx = -1e30f;
            for (int m = 0; m < MN; m++) mx = fmaxf(mx, q0[tid*MN + m]);
            float s = 0.f, e[MN];
            for (int m = 0; m < MN; m++) { e[m] = expf(q0[tid*MN + m] - mx); s += e[m]; }
            for (int m = 0; m < MN; m++) g_q[tid*MN + m] = e[m] / s;
        }
        if (tid < T*MN) {
            int t = tid / MN, j = tid % MN;
            float mx = -1e30f;
            for (int i = 0; i < MN; i++) mx = fmaxf(mx, tmpl[(t*MN + i)*MN + j]);
            float s = 0.f, e[MN];
            for (int i = 0; i < MN; i++) { e[i] = expf(tmpl[(t*MN + i)*MN + j] - mx); s += e[i]; }
            for (int i = 0; i < MN; i++) g_C2[(t*MN + i)*MN + j] = e[i] / s;
        }
        if (tid < T*MN) {
            float s = 0.f;
            const float4* row = (const float4*)(tf + (size_t)tid * D);
            #pragma unroll 8
            for (int d = 0; d < D/4; d++) {
                float4 v = row[d];
                s += v.x*v.x + v.y*v.y + v.z*v.z + v.w*v.w;
            }
            g_f2sq[tid] = s;
        }
        __syncthreads();
        if (tid < T*MN) {
            int t = tid / MN, l = tid % MN;
            float s = 0.f, hq = 0.f;
            for (int k = 0; k < MN; k++) {
                float c = g_C2[(t*MN + l)*MN + k];
                float qq = g_q[t*MN + k];
                s += c * c * qq;
                hq += c * qq;
            }
            g_hC2[tid] = s;
            g_Hq[tid]  = hq;
        }
    }
}

// ---------------- kernel 2: FGW — R15 base, trimmed syncs ------------------
__global__ __launch_bounds__(320, 4) void ltfgw_kernel(const int* __restrict__ dst,
                                                       float* __restrict__ out) {
    __shared__ __align__(16) float sC2[T][MN][12];    // zero-padded rows
    __shared__ __align__(16) float grows[T][18][12];  // K/G rows; row 17 = zero pad
    __shared__ __align__(16) float eargs[T][S][12];   // outer-invariant exponent bases
    __shared__ __align__(16) float vbuf[T][12];
    __shared__ __align__(16) float wbuf[T][24];       // rows 0-8 @[0..8]; 9-16 @[12..19]; [20..23]=0
    __shared__ __align__(16) float h0buf[T][2][12];   // double-buffered extras scratch
    __shared__ __align__(16) float sHq[T][12];
    __shared__ __align__(16) float shC2[T][12];
    __shared__ __align__(16) float sF2[T][12];
    __shared__ __align__(16) float sq_[T][12];
    __shared__ unsigned smask[S];
    __shared__ int ids[S];

    int n = blockIdx.x, tid = threadIdx.x;

    if (tid < S) {
        ids[tid] = (tid == 0) ? n : dst[n*DEG + tid - 1];
        smask[tid] = 0u;
    }
    for (int idx = tid; idx < T*MN*12; idx += 320) {
        int t0 = idx / (MN*12), rem = idx % (MN*12);
        int l0 = rem / 12, k0 = rem % 12;
        ((float*)sC2)[idx] = (k0 < MN) ? g_C2[(t0*MN + l0)*MN + k0] : 0.f;
    }
    for (int idx = tid; idx < T*MN; idx += 320) {
        int t0 = idx / MN, l0 = idx % MN;
        sHq[t0][l0]  = g_Hq[idx];
        shC2[t0][l0] = g_hC2[idx];
        sF2[t0][l0]  = g_f2sq[idx];
        sq_[t0][l0]  = g_q[idx];
    }
    // zero padding: grows row 17, wbuf[20..23]
    if (tid < T*12) grows[tid/12][17][tid%12] = 0.f;
    if (tid < T*4)  wbuf[tid/4][20 + (tid%4)] = 0.f;
    __syncthreads();

    for (int e = tid; e < S*DEG; e += 320) {
        int a = e / DEG, k = e % DEG;
        int nb = dst[ids[a]*DEG + k];
        #pragma unroll
        for (int b = 0; b < S; b++) {
            if (ids[b] == nb) { atomicOr(&smask[a], 1u << b); atomicOr(&smask[b], 1u << a); }
        }
    }
    __syncthreads();
    if (tid < S) smask[tid] &= ~(1u << tid);
    __syncthreads();

    const float alpha = g_alpha;
    const float oma = 1.0f - alpha;
    const float cE = (1.0f/EPS) * LOG2E;
    const float invcE = EPS * LN2;
    const float c3 = 4.0f * alpha * (1.0f/EPS) * LOG2E;
    const float m2a = -2.0f * alpha;

    int t = tid >> 5, lane = tid & 31;
    bool rowact = lane < S;
    bool colact = lane < MN;
    int ei   = rowact ? lane : (S-1);
    int hidx = colact ? lane : MN;
    int hi   = (lane >> 4) & 1;                  // half-warp selector for split KT
    int colsel = hi ? (lane - 16) : lane;
    colsel = (colsel < MN) ? colsel : 0;
    int woff = hi * 12;
    int ktbase = hi * 9;
    unsigned mask_i = rowact ? smask[lane] : 0u;
    float hc1 = __popc(mask_i) * (1.0f / S);
    unsigned extra = (lane == 0 || !rowact) ? 0u : (mask_i & ~1u);
    unsigned Uall = __reduce_or_sync(FULLMASK, extra);

    // setup: Earg rows into smem (outer-0's A is closed form: A = hc1 * Hq)
    float Fbase = 0.f;
    if (rowact) {
        int id = ids[lane];
        float xs = g_xsq[id];
        const float2* pm2 = (const float2*)(g_Pm + (size_t)id*TM + t*MN);
        float pmv[MN];
        #pragma unroll
        for (int h = 0; h < 5; h++) { float2 p = __ldg(&pm2[h]); pmv[2*h] = p.x; pmv[2*h+1] = p.y; }
        float M0 = xs + sF2[t][0] + pmv[0];
        Fbase = oma * M0;
        float e[MN];
        #pragma unroll
        for (int l = 0; l < MN; l++) {
            float Ml = xs + sF2[t][l] + pmv[l];
            float hh = hc1 + shC2[t][l];
            e[l] = (oma*(M0 - Ml) - 2.f*alpha*hh) * cE;
        }
        *(float4*)&eargs[t][lane][0] = make_float4(e[0],e[1],e[2],e[3]);
        *(float4*)&eargs[t][lane][4] = make_float4(e[4],e[5],e[6],e[7]);
        *(float2*)&eargs[t][lane][8] = make_float2(e[8],e[9]);
    }
    float qcol = sq_[t][colsel];

    float Kw[MN];      // own kernel row (rebuilt per outer)
    float w = 0.f;     // own row scaling

    for (int it = 0; it <= N_OUTER; it++) {
        __syncwarp();   // fold / setup stores visible
        float A[MN];
        if (it == 0) {
            // outer-0 shortcut: G0 = p q^T -> A_i = hc1 * Hq (all rows)
            float4 q0v = *(const float4*)&sHq[t][0];
            float4 q1v = *(const float4*)&sHq[t][4];
            float2 q2v = *(const float2*)&sHq[t][8];
            A[0]=hc1*q0v.x; A[1]=hc1*q0v.y; A[2]=hc1*q0v.z; A[3]=hc1*q0v.w;
            A[4]=hc1*q1v.x; A[5]=hc1*q1v.y; A[6]=hc1*q1v.z; A[7]=hc1*q1v.w;
            A[8]=hc1*q2v.x; A[9]=hc1*q2v.y;
        } else {
            // ---- H0 (column-marginal identity), branchless ----
            int lc = colact ? lane : 0;
            float4 c0 = *(const float4*)&sC2[t][lc][0];
            float4 c1 = *(const float4*)&sC2[t][lc][4];
            float2 c2v = *(const float2*)&sC2[t][lc][8];
            {
                float4 ga = *(const float4*)&grows[t][0][0];
                float4 gb = *(const float4*)&grows[t][0][4];
                float2 gc = *(const float2*)&grows[t][0][8];
                float h = ga.x*c0.x + ga.y*c0.y + ga.z*c0.z + ga.w*c0.w
                        + gb.x*c1.x + gb.y*c1.y + gb.z*c1.z + gb.w*c1.w
                        + gc.x*c2v.x + gc.y*c2v.y;
                h0buf[t][0][hidx] = h;
            }
            __syncwarp();
            {
                float4 a0 = *(const float4*)&h0buf[t][0][0];
                float4 a1 = *(const float4*)&h0buf[t][0][4];
                float2 a2 = *(const float2*)&h0buf[t][0][8];
                A[0]=a0.x; A[1]=a0.y; A[2]=a0.z; A[3]=a0.w;
                A[4]=a1.x; A[5]=a1.y; A[6]=a1.z; A[7]=a1.w;
                A[8]=a2.x; A[9]=a2.y;
            }
            if (lane == 0) {
                float4 q0v = *(const float4*)&sHq[t][0];
                float4 q1v = *(const float4*)&sHq[t][4];
                float2 q2v = *(const float2*)&sHq[t][8];
                A[0]=q0v.x-A[0]; A[1]=q0v.y-A[1]; A[2]=q0v.z-A[2]; A[3]=q0v.w-A[3];
                A[4]=q1v.x-A[4]; A[5]=q1v.y-A[5]; A[6]=q1v.z-A[6]; A[7]=q1v.w-A[7];
                A[8]=q2v.x-A[8]; A[9]=q2v.y-A[9];
            }
            // ---- rare extras: double-buffered, one sync per extra ----
            unsigned U = Uall;
            int buf = 1;
            while (U) {
                int j = __ffs(U) - 1;
                U &= U - 1u;
                float4 ja = *(const float4*)&grows[t][j][0];
                float4 jb = *(const float4*)&grows[t][j][4];
                float2 jc = *(const float2*)&grows[t][j][8];
                float hj = ja.x*c0.x + ja.y*c0.y + ja.z*c0.z + ja.w*c0.w
                         + jb.x*c1.x + jb.y*c1.y + jb.z*c1.z + jb.w*c1.w
                         + jc.x*c2v.x + jc.y*c2v.y;
                h0buf[t][buf][hidx] = hj;
                __syncwarp();
                bool add = (extra >> j) & 1u;
                float4 a0 = *(const float4*)&h0buf[t][buf][0];
                float4 a1 = *(const float4*)&h0buf[t][buf][4];
                float2 a2 = *(const float2*)&h0buf[t][buf][8];
                if (add) {
                    A[0]+=a0.x; A[1]+=a0.y; A[2]+=a0.z; A[3]+=a0.w;
                    A[4]+=a1.x; A[5]+=a1.y; A[6]+=a1.z; A[7]+=a1.w;
                    A[8]+=a2.x; A[9]+=a2.y;
                }
                buf ^= 1;
            }
        }

        if (it == N_OUTER) {
            float acc = 0.f;
            if (rowact) {
                float4 g0 = *(const float4*)&grows[t][lane][0];
                float4 g1 = *(const float4*)&grows[t][lane][4];
                float2 g2 = *(const float2*)&grows[t][lane][8];
                float4 e0 = *(const float4*)&eargs[t][lane][0];
                float4 e1 = *(const float4*)&eargs[t][lane][4];
                float2 e2 = *(const float2*)&eargs[t][lane][8];
                float4 h0v = *(const float4*)&shC2[t][0];
                float4 h1v = *(const float4*)&shC2[t][4];
                float2 h2v = *(const float2*)&shC2[t][8];
                float gg[MN] = {g0.x,g0.y,g0.z,g0.w,g1.x,g1.y,g1.z,g1.w,g2.x,g2.y};
                float ee[MN] = {e0.x,e0.y,e0.z,e0.w,e1.x,e1.y,e1.z,e1.w,e2.x,e2.y};
                float hh[MN] = {h0v.x,h0v.y,h0v.z,h0v.w,h1v.x,h1v.y,h1v.z,h1v.w,h2v.x,h2v.y};
                #pragma unroll
                for (int l = 0; l < MN; l++) {
                    float Fl = Fbase - ee[l]*invcE - alpha*(hc1 + hh[l]);
                    acc += gg[l] * fmaf(m2a, A[l], Fl);
                }
            }
            acc += __shfl_xor_sync(FULLMASK, acc, 16);
            acc += __shfl_xor_sync(FULLMASK, acc, 8);
            acc += __shfl_xor_sync(FULLMASK, acc, 4);
            acc += __shfl_xor_sync(FULLMASK, acc, 2);
            acc += __shfl_xor_sync(FULLMASK, acc, 1);
            if (lane == 0) out[n*T + t] = acc;
            return;
        }

        // ---- Kw = exp2(c3*A + Earg) (row-shifted kernel) ----
        {
            float4 e0 = *(const float4*)&eargs[t][ei][0];
            float4 e1 = *(const float4*)&eargs[t][ei][4];
            float2 e2 = *(const float2*)&eargs[t][ei][8];
            float ee[MN] = {e0.x,e0.y,e0.z,e0.w,e1.x,e1.y,e1.z,e1.w,e2.x,e2.y};
            #pragma unroll
            for (int l = 0; l < MN; l++) Kw[l] = ex2(fmaf(c3, A[l], ee[l]));
        }

        // ---- stage K rows into grows, pull split-KT ----
        // (no pre-staging syncwarp: on every path the last grows read is
        //  already ordered by an h0buf __syncwarp; outer 0 reads none)
        if (rowact) {
            *(float4*)&grows[t][lane][0] = make_float4(Kw[0],Kw[1],Kw[2],Kw[3]);
            *(float4*)&grows[t][lane][4] = make_float4(Kw[4],Kw[5],Kw[6],Kw[7]);
            *(float2*)&grows[t][lane][8] = make_float2(Kw[8],Kw[9]);
        }
        __syncwarp();
        float KT[9];
        #pragma unroll
        for (int ii = 0; ii < 9; ii++) KT[ii] = grows[t][ktbase + ii][colsel];

        // ---- Sinkhorn (scaling domain): split col sums + shfl combine ----
        {   // iter 1 peeled (v == 1)
            float rs = Kw[0]+Kw[1]+Kw[2]+Kw[3]+Kw[4]+Kw[5]+Kw[6]+Kw[7]+Kw[8]+Kw[9];
            w = __fdividef(1.0f / S, rs);
            if (rowact) wbuf[t][lane < 9 ? lane : lane + 3] = w;
            __syncwarp();
            float4 wa = *(const float4*)&wbuf[t][woff];
            float4 wb = *(const float4*)&wbuf[t][woff+4];
            float  wc = wbuf[t][woff+8];
            float part = KT[0]*wa.x + KT[1]*wa.y + KT[2]*wa.z + KT[3]*wa.w
                       + KT[4]*wb.x + KT[5]*wb.y + KT[6]*wb.z + KT[7]*wb.w
                       + KT[8]*wc;
            float cs = part + __shfl_xor_sync(FULLMASK, part, 16);
            float vnew = __fdividef(qcol, cs);
            if (colact) vbuf[t][lane] = vnew;
            __syncwarp();
        }
        #pragma unroll
        for (int si = 1; si < N_SINK; si++) {
            float4 b0 = *(const float4*)&vbuf[t][0];
            float4 b1 = *(const float4*)&vbuf[t][4];
            float2 b2 = *(const float2*)&vbuf[t][8];
            float rs = Kw[0]*b0.x + Kw[1]*b0.y + Kw[2]*b0.z + Kw[3]*b0.w
                     + Kw[4]*b1.x + Kw[5]*b1.y + Kw[6]*b1.z + Kw[7]*b1.w
                     + Kw[8]*b2.x + Kw[9]*b2.y;
            w = __fdividef(1.0f / S, rs);
            if (rowact) wbuf[t][lane < 9 ? lane : lane + 3] = w;
            __syncwarp();
            float4 wa = *(const float4*)&wbuf[t][woff];
            float4 wb = *(const float4*)&wbuf[t][woff+4];
            float  wc = wbuf[t][woff+8];
            float part = KT[0]*wa.x + KT[1]*wa.y + KT[2]*wa.z + KT[3]*wa.w
                       + KT[4]*wb.x + KT[5]*wb.y + KT[6]*wb.z + KT[7]*wb.w
                       + KT[8]*wc;
            float cs = part + __shfl_xor_sync(FULLMASK, part, 16);
            float vnew = __fdividef(qcol, cs);
            if (colact) vbuf[t][lane] = vnew;
            __syncwarp();
        }

        // ---- fold: rows read next outer (row 0 + extras); full on last ----
        {
            float4 b0 = *(const float4*)&vbuf[t][0];
            float4 b1 = *(const float4*)&vbuf[t][4];
            float2 b2 = *(const float2*)&vbuf[t][8];
            bool nf = rowact && ((lane == 0) || ((Uall >> lane) & 1u) || (it == N_OUTER - 1));
            if (nf) {
                *(float4*)&grows[t][lane][0] = make_float4(w*Kw[0]*b0.x, w*Kw[1]*b0.y, w*Kw[2]*b0.z, w*Kw[3]*b0.w);
                *(float4*)&grows[t][lane][4] = make_float4(w*Kw[4]*b1.x, w*Kw[5]*b1.y, w*Kw[6]*b1.z, w*Kw[7]*b1.w);
                *(float2*)&grows[t][lane][8] = make_float2(w*Kw[8]*b2.x, w*Kw[9]*b2.y);
            }
        }
    }
}

// ---------------- launch ----------------------------------------------------
extern "C" void kernel_launch(void* const* d_in, const int* in_sizes, int n_in,
                              void* d_out, int out_size) {
    const float* x      = (const float*)d_in[0];
    const int*   edge   = (const int*)  d_in[1];
    const float* tmpl   = (const float*)d_in[2];
    const float* tf     = (const float*)d_in[3];
    const float* q0     = (const float*)d_in[4];
    const float* alpha0 = (const float*)d_in[5];
    const int*   dst    = edge + N_NODES*DEG;
    float* out = (float*)d_out;

    pm_pre_kernel<<<N_NODES/NPB, 256>>>(x, tf, tmpl, q0, alpha0);
    ltfgw_kernel<<<N_NODES, 320>>>(dst, out);
}

// round 17
// speedup vs baseline: 1.0491x; 1.0491x over previous
#include <cuda_runtime.h>
#include <math.h>

#define N_NODES 5000
#define DEG 16
#define S 17
#define T 10
#define MN 10
#define D 128
#define EPS 0.1f
#define N_OUTER 3
#define N_SINK 5
#define TM 100
#define NPB 20
#define LOG2E 1.4426950408889634f
#define LN2 0.6931471805599453f
#define FULLMASK 0xffffffffu

__device__ __forceinline__ float ex2(float x) {
    float r; asm("ex2.approx.ftz.f32 %0, %1;" : "=f"(r) : "f"(x)); return r;
}

// ---------------- device-global precomputed state / scratch ----------------
__device__ float g_alpha;
__device__ float g_C2[T*MN*MN];
__device__ float g_q[T*MN];
__device__ float g_hC2[T*MN];
__device__ float g_Hq[T*MN];
__device__ float g_f2sq[T*MN];
__device__ float g_Pm[(size_t)N_NODES * TM];   // -2<x_n,F2_tm>
__device__ float g_xsq[N_NODES];

// ---------------- kernel 1: Pm GEMM + fused precompute (block 0) ----------
// (R15 shape: NPB=20 / 512 threads / 250 blocks — measured best)
__global__ __launch_bounds__(512) void pm_pre_kernel(const float* __restrict__ x,
                                                     const float* __restrict__ tf,
                                                     const float* __restrict__ tmpl,
                                                     const float* __restrict__ q0,
                                                     const float* __restrict__ alpha0) {
    __shared__ __align__(16) float4 sx4[NPB][D/4 + 1];
    int base = blockIdx.x * NPB;
    int tid = threadIdx.x;

    for (int idx = tid; idx < NPB*(D/4); idx += 512) {
        int r = idx / (D/4), c = idx % (D/4);
        sx4[r][c] = ((const float4*)(x + (size_t)(base + r)*D))[c];
    }
    __syncthreads();
    if (tid < NPB) {
        float s = 0.f;
        #pragma unroll 8
        for (int d = 0; d < D/4; d++) {
            float4 v = sx4[tid][d];
            s += v.x*v.x + v.y*v.y + v.z*v.z + v.w*v.w;
        }
        g_xsq[base + tid] = s;
    }
    if (tid < NPB * (TM/4)) {
        int nl = tid % NPB, tm0 = (tid / NPB) * 4;
        const float4* b0 = (const float4*)(tf + (size_t)(tm0+0)*D);
        const float4* b1 = (const float4*)(tf + (size_t)(tm0+1)*D);
        const float4* b2 = (const float4*)(tf + (size_t)(tm0+2)*D);
        const float4* b3 = (const float4*)(tf + (size_t)(tm0+3)*D);
        float a0=0.f, a1=0.f, a2=0.f, a3=0.f;
        #pragma unroll 8
        for (int d = 0; d < D/4; d++) {
            float4 av = sx4[nl][d];
            float4 r0 = b0[d], r1 = b1[d], r2 = b2[d], r3 = b3[d];
            a0 += av.x*r0.x + av.y*r0.y + av.z*r0.z + av.w*r0.w;
            a1 += av.x*r1.x + av.y*r1.y + av.z*r1.z + av.w*r1.w;
            a2 += av.x*r2.x + av.y*r2.y + av.z*r2.z + av.w*r2.w;
            a3 += av.x*r3.x + av.y*r3.y + av.z*r3.z + av.w*r3.w;
        }
        size_t o = (size_t)(base + nl)*TM + tm0;
        g_Pm[o+0] = -2.f*a0; g_Pm[o+1] = -2.f*a1;
        g_Pm[o+2] = -2.f*a2; g_Pm[o+3] = -2.f*a3;
    }

    if (blockIdx.x == 0) {
        if (tid == 0) g_alpha = 1.0f / (1.0f + expf(-alpha0[0]));
        if (tid < T) {
            float mx = -1e30f;
            for (int m = 0; m < MN; m++) mx = fmaxf(mx, q0[tid*MN + m]);
            float s = 0.f, e[MN];
            for (int m = 0; m < MN; m++) { e[m] = expf(q0[tid*MN + m] - mx); s += e[m]; }
            for (int m = 0; m < MN; m++) g_q[tid*MN + m] = e[m] / s;
        }
        if (tid < T*MN) {
            int t = tid / MN, j = tid % MN;
            float mx = -1e30f;
            for (int i = 0; i < MN; i++) mx = fmaxf(mx, tmpl[(t*MN + i)*MN + j]);
            float s = 0.f, e[MN];
            for (int i = 0; i < MN; i++) { e[i] = expf(tmpl[(t*MN + i)*MN + j] - mx); s += e[i]; }
            for (int i = 0; i < MN; i++) g_C2[(t*MN + i)*MN + j] = e[i] / s;
        }
        if (tid < T*MN) {
            float s = 0.f;
            const float4* row = (const float4*)(tf + (size_t)tid * D);
            #pragma unroll 8
            for (int d = 0; d < D/4; d++) {
                float4 v = row[d];
                s += v.x*v.x + v.y*v.y + v.z*v.z + v.w*v.w;
            }
            g_f2sq[tid] = s;
        }
        __syncthreads();
        if (tid < T*MN) {
            int t = tid / MN, l = tid % MN;
            float s = 0.f, hq = 0.f;
            for (int k = 0; k < MN; k++) {
                float c = g_C2[(t*MN + l)*MN + k];
                float qq = g_q[t*MN + k];
                s += c * c * qq;
                hq += c * qq;
            }
            g_hC2[tid] = s;
            g_Hq[tid]  = hq;
        }
    }
}

// ---------------- shared Sinkhorn phase (macro'd into each outer) ----------
// Stages Kw into grows, pulls split-KT, runs N_SINK scaling iterations.
// Leaves w in `w`, v in vbuf, staged K in grows.

// ---------------- kernel 2: FGW — R15 base, outer-0 peeled -----------------
__global__ __launch_bounds__(320, 4) void ltfgw_kernel(const int* __restrict__ dst,
                                                       float* __restrict__ out) {
    __shared__ __align__(16) float sC2[T][MN][12];    // zero-padded rows
    __shared__ __align__(16) float grows[T][18][12];  // K/G rows; row 17 = zero pad
    __shared__ __align__(16) float eargs[T][S][12];   // outer-invariant exponent bases
    __shared__ __align__(16) float vbuf[T][12];
    __shared__ __align__(16) float wbuf[T][24];       // rows 0-8 @[0..8]; 9-16 @[12..19]; [20..23]=0
    __shared__ __align__(16) float h0buf[T][12];
    __shared__ __align__(16) float sHq[T][12];
    __shared__ __align__(16) float shC2[T][12];
    __shared__ __align__(16) float sF2[T][12];
    __shared__ __align__(16) float sq_[T][12];
    __shared__ unsigned smask[S];
    __shared__ int ids[S];

    int n = blockIdx.x, tid = threadIdx.x;

    if (tid < S) {
        ids[tid] = (tid == 0) ? n : dst[n*DEG + tid - 1];
        smask[tid] = 0u;
    }
    for (int idx = tid; idx < T*MN*12; idx += 320) {
        int t0 = idx / (MN*12), rem = idx % (MN*12);
        int l0 = rem / 12, k0 = rem % 12;
        ((float*)sC2)[idx] = (k0 < MN) ? g_C2[(t0*MN + l0)*MN + k0] : 0.f;
    }
    for (int idx = tid; idx < T*MN; idx += 320) {
        int t0 = idx / MN, l0 = idx % MN;
        sHq[t0][l0]  = g_Hq[idx];
        shC2[t0][l0] = g_hC2[idx];
        sF2[t0][l0]  = g_f2sq[idx];
        sq_[t0][l0]  = g_q[idx];
    }
    // zero padding: grows row 17, wbuf[20..23]
    if (tid < T*12) grows[tid/12][17][tid%12] = 0.f;
    if (tid < T*4)  wbuf[tid/4][20 + (tid%4)] = 0.f;
    __syncthreads();

    for (int e = tid; e < S*DEG; e += 320) {
        int a = e / DEG, k = e % DEG;
        int nb = dst[ids[a]*DEG + k];
        #pragma unroll
        for (int b = 0; b < S; b++) {
            if (ids[b] == nb) { atomicOr(&smask[a], 1u << b); atomicOr(&smask[b], 1u << a); }
        }
    }
    __syncthreads();
    if (tid < S) smask[tid] &= ~(1u << tid);
    __syncthreads();

    const float alpha = g_alpha;
    const float oma = 1.0f - alpha;
    const float cE = (1.0f/EPS) * LOG2E;
    const float invcE = EPS * LN2;
    const float c3 = 4.0f * alpha * (1.0f/EPS) * LOG2E;
    const float m2a = -2.0f * alpha;

    int t = tid >> 5, lane = tid & 31;
    bool rowact = lane < S;
    bool colact = lane < MN;
    int ei   = rowact ? lane : (S-1);
    int hidx = colact ? lane : MN;
    int hi   = (lane >> 4) & 1;                  // half-warp selector for split KT
    int colsel = hi ? (lane - 16) : lane;
    colsel = (colsel < MN) ? colsel : 0;
    int woff = hi * 12;
    int ktbase = hi * 9;
    unsigned mask_i = rowact ? smask[lane] : 0u;
    float hc1 = __popc(mask_i) * (1.0f / S);
    unsigned extra = (lane == 0 || !rowact) ? 0u : (mask_i & ~1u);
    unsigned Uall = __reduce_or_sync(FULLMASK, extra);

    // setup: Earg rows into smem (outer-0's A is closed form: A = hc1 * Hq)
    float Fbase = 0.f;
    if (rowact) {
        int id = ids[lane];
        float xs = g_xsq[id];
        const float2* pm2 = (const float2*)(g_Pm + (size_t)id*TM + t*MN);
        float pmv[MN];
        #pragma unroll
        for (int h = 0; h < 5; h++) { float2 p = __ldg(&pm2[h]); pmv[2*h] = p.x; pmv[2*h+1] = p.y; }
        float M0 = xs + sF2[t][0] + pmv[0];
        Fbase = oma * M0;
        float e[MN];
        #pragma unroll
        for (int l = 0; l < MN; l++) {
            float Ml = xs + sF2[t][l] + pmv[l];
            float hh = hc1 + shC2[t][l];
            e[l] = (oma*(M0 - Ml) - 2.f*alpha*hh) * cE;
        }
        *(float4*)&eargs[t][lane][0] = make_float4(e[0],e[1],e[2],e[3]);
        *(float4*)&eargs[t][lane][4] = make_float4(e[4],e[5],e[6],e[7]);
        *(float2*)&eargs[t][lane][8] = make_float2(e[8],e[9]);
    }
    float qcol = sq_[t][colsel];

    float Kw[MN];
    float w = 0.f;
    float A[MN];

// ---- Sinkhorn + staging block (identical instruction stream each use) ----
#define STAGE_AND_SINKHORN(FULL_FOLD)                                          \
    {                                                                          \
        float4 e0 = *(const float4*)&eargs[t][ei][0];                          \
        float4 e1 = *(const float4*)&eargs[t][ei][4];                          \
        float2 e2 = *(const float2*)&eargs[t][ei][8];                          \
        float ee[MN] = {e0.x,e0.y,e0.z,e0.w,e1.x,e1.y,e1.z,e1.w,e2.x,e2.y};    \
        _Pragma("unroll")                                                      \
        for (int l = 0; l < MN; l++) Kw[l] = ex2(fmaf(c3, A[l], ee[l]));       \
    }                                                                          \
    __syncwarp();                                                              \
    if (rowact) {                                                              \
        *(float4*)&grows[t][lane][0] = make_float4(Kw[0],Kw[1],Kw[2],Kw[3]);   \
        *(float4*)&grows[t][lane][4] = make_float4(Kw[4],Kw[5],Kw[6],Kw[7]);   \
        *(float2*)&grows[t][lane][8] = make_float2(Kw[8],Kw[9]);               \
    }                                                                          \
    __syncwarp();                                                              \
    float KT[9];                                                               \
    _Pragma("unroll")                                                          \
    for (int ii = 0; ii < 9; ii++) KT[ii] = grows[t][ktbase + ii][colsel];     \
    {   /* iter 1 peeled (v == 1) */                                           \
        float rs = Kw[0]+Kw[1]+Kw[2]+Kw[3]+Kw[4]+Kw[5]+Kw[6]+Kw[7]+Kw[8]+Kw[9];\
        w = __fdividef(1.0f / S, rs);                                          \
        if (rowact) wbuf[t][lane < 9 ? lane : lane + 3] = w;                   \
        __syncwarp();                                                          \
        float4 wa = *(const float4*)&wbuf[t][woff];                            \
        float4 wb = *(const float4*)&wbuf[t][woff+4];                          \
        float  wc = wbuf[t][woff+8];                                           \
        float part = KT[0]*wa.x + KT[1]*wa.y + KT[2]*wa.z + KT[3]*wa.w         \
                   + KT[4]*wb.x + KT[5]*wb.y + KT[6]*wb.z + KT[7]*wb.w         \
                   + KT[8]*wc;                                                 \
        float cs = part + __shfl_xor_sync(FULLMASK, part, 16);                 \
        float vnew = __fdividef(qcol, cs);                                     \
        if (colact) vbuf[t][lane] = vnew;                                      \
        __syncwarp();                                                          \
    }                                                                          \
    _Pragma("unroll")                                                          \
    for (int si = 1; si < N_SINK; si++) {                                      \
        float4 b0 = *(const float4*)&vbuf[t][0];                               \
        float4 b1 = *(const float4*)&vbuf[t][4];                               \
        float2 b2 = *(const float2*)&vbuf[t][8];                               \
        float rs = Kw[0]*b0.x + Kw[1]*b0.y + Kw[2]*b0.z + Kw[3]*b0.w           \
                 + Kw[4]*b1.x + Kw[5]*b1.y + Kw[6]*b1.z + Kw[7]*b1.w           \
                 + Kw[8]*b2.x + Kw[9]*b2.y;                                    \
        w = __fdividef(1.0f / S, rs);                                          \
        if (rowact) wbuf[t][lane < 9 ? lane : lane + 3] = w;                   \
        __syncwarp();                                                          \
        float4 wa = *(const float4*)&wbuf[t][woff];                            \
        float4 wb = *(const float4*)&wbuf[t][woff+4];                          \
        float  wc = wbuf[t][woff+8];                                           \
        float part = KT[0]*wa.x + KT[1]*wa.y + KT[2]*wa.z + KT[3]*wa.w         \
                   + KT[4]*wb.x + KT[5]*wb.y + KT[6]*wb.z + KT[7]*wb.w         \
                   + KT[8]*wc;                                                 \
        float cs = part + __shfl_xor_sync(FULLMASK, part, 16);                 \
        float vnew = __fdividef(qcol, cs);                                     \
        if (colact) vbuf[t][lane] = vnew;                                      \
        __syncwarp();                                                          \
    }                                                                          \
    {                                                                          \
        float4 b0 = *(const float4*)&vbuf[t][0];                               \
        float4 b1 = *(const float4*)&vbuf[t][4];                               \
        float2 b2 = *(const float2*)&vbuf[t][8];                               \
        bool nf = rowact && ((lane == 0) || ((Uall >> lane) & 1u) || (FULL_FOLD)); \
        if (nf) {                                                              \
            *(float4*)&grows[t][lane][0] = make_float4(w*Kw[0]*b0.x, w*Kw[1]*b0.y, w*Kw[2]*b0.z, w*Kw[3]*b0.w); \
            *(float4*)&grows[t][lane][4] = make_float4(w*Kw[4]*b1.x, w*Kw[5]*b1.y, w*Kw[6]*b1.z, w*Kw[7]*b1.w); \
            *(float2*)&grows[t][lane][8] = make_float2(w*Kw[8]*b2.x, w*Kw[9]*b2.y); \
        }                                                                      \
    }

// ---- H-phase: A from current G (grows), col-marginal identity + extras ----
#define H_PHASE()                                                              \
    __syncwarp();   /* fold stores visible */                                  \
    {                                                                          \
        int lc = colact ? lane : 0;                                            \
        float4 c0 = *(const float4*)&sC2[t][lc][0];                            \
        float4 c1 = *(const float4*)&sC2[t][lc][4];                            \
        float2 c2v = *(const float2*)&sC2[t][lc][8];                           \
        {                                                                      \
            float4 ga = *(const float4*)&grows[t][0][0];                       \
            float4 gb = *(const float4*)&grows[t][0][4];                       \
            float2 gc = *(const float2*)&grows[t][0][8];                       \
            float h = ga.x*c0.x + ga.y*c0.y + ga.z*c0.z + ga.w*c0.w            \
                    + gb.x*c1.x + gb.y*c1.y + gb.z*c1.z + gb.w*c1.w            \
                    + gc.x*c2v.x + gc.y*c2v.y;                                 \
            h0buf[t][hidx] = h;                                                \
        }                                                                      \
        __syncwarp();                                                          \
        {                                                                      \
            float4 a0 = *(const float4*)&h0buf[t][0];                          \
            float4 a1 = *(const float4*)&h0buf[t][4];                          \
            float2 a2 = *(const float2*)&h0buf[t][8];                          \
            A[0]=a0.x; A[1]=a0.y; A[2]=a0.z; A[3]=a0.w;                        \
            A[4]=a1.x; A[5]=a1.y; A[6]=a1.z; A[7]=a1.w;                        \
            A[8]=a2.x; A[9]=a2.y;                                              \
        }                                                                      \
        if (lane == 0) {                                                       \
            float4 q0v = *(const float4*)&sHq[t][0];                           \
            float4 q1v = *(const float4*)&sHq[t][4];                           \
            float2 q2v = *(const float2*)&sHq[t][8];                           \
            A[0]=q0v.x-A[0]; A[1]=q0v.y-A[1]; A[2]=q0v.z-A[2]; A[3]=q0v.w-A[3];\
            A[4]=q1v.x-A[4]; A[5]=q1v.y-A[5]; A[6]=q1v.z-A[6]; A[7]=q1v.w-A[7];\
            A[8]=q2v.x-A[8]; A[9]=q2v.y-A[9];                                  \
        }                                                                      \
        unsigned U = Uall;                                                     \
        while (U) {                                                            \
            int j = __ffs(U) - 1;                                              \
            U &= U - 1u;                                                       \
            __syncwarp();                                                      \
            float4 ja = *(const float4*)&grows[t][j][0];                       \
            float4 jb = *(const float4*)&grows[t][j][4];                       \
            float2 jc = *(const float2*)&grows[t][j][8];                       \
            float hj = ja.x*c0.x + ja.y*c0.y + ja.z*c0.z + ja.w*c0.w           \
                     + jb.x*c1.x + jb.y*c1.y + jb.z*c1.z + jb.w*c1.w           \
                     + jc.x*c2v.x + jc.y*c2v.y;                                \
            h0buf[t][hidx] = hj;                                               \
            __syncwarp();                                                      \
            bool add = (extra >> j) & 1u;                                      \
            float4 a0 = *(const float4*)&h0buf[t][0];                          \
            float4 a1 = *(const float4*)&h0buf[t][4];                          \
            float2 a2 = *(const float2*)&h0buf[t][8];                          \
            if (add) {                                                         \
                A[0]+=a0.x; A[1]+=a0.y; A[2]+=a0.z; A[3]+=a0.w;                \
                A[4]+=a1.x; A[5]+=a1.y; A[6]+=a1.z; A[7]+=a1.w;                \
                A[8]+=a2.x; A[9]+=a2.y;                                        \
            }                                                                  \
        }                                                                      \
    }

    // ================= outer 0 (peeled): A = hc1 * Hq =================
    {
        float4 q0v = *(const float4*)&sHq[t][0];
        float4 q1v = *(const float4*)&sHq[t][4];
        float2 q2v = *(const float2*)&sHq[t][8];
        A[0]=hc1*q0v.x; A[1]=hc1*q0v.y; A[2]=hc1*q0v.z; A[3]=hc1*q0v.w;
        A[4]=hc1*q1v.x; A[5]=hc1*q1v.y; A[6]=hc1*q1v.z; A[7]=hc1*q1v.w;
        A[8]=hc1*q2v.x; A[9]=hc1*q2v.y;
    }
    {
        STAGE_AND_SINKHORN(false)
    }

    // ================= outers 1 .. N_OUTER-1 =================
    for (int it = 1; it < N_OUTER; it++) {
        H_PHASE()
        bool fullFold = (it == N_OUTER - 1);
        STAGE_AND_SINKHORN(fullFold)
    }

    // ================= final: tens with final G, distance =================
    H_PHASE()
    {
        float acc = 0.f;
        if (rowact) {
            float4 g0 = *(const float4*)&grows[t][lane][0];
            float4 g1 = *(const float4*)&grows[t][lane][4];
            float2 g2 = *(const float2*)&grows[t][lane][8];
            float4 e0 = *(const float4*)&eargs[t][lane][0];
            float4 e1 = *(const float4*)&eargs[t][lane][4];
            float2 e2 = *(const float2*)&eargs[t][lane][8];
            float4 h0v = *(const float4*)&shC2[t][0];
            float4 h1v = *(const float4*)&shC2[t][4];
            float2 h2v = *(const float2*)&shC2[t][8];
            float gg[MN] = {g0.x,g0.y,g0.z,g0.w,g1.x,g1.y,g1.z,g1.w,g2.x,g2.y};
            float ee[MN] = {e0.x,e0.y,e0.z,e0.w,e1.x,e1.y,e1.z,e1.w,e2.x,e2.y};
            float hh[MN] = {h0v.x,h0v.y,h0v.z,h0v.w,h1v.x,h1v.y,h1v.z,h1v.w,h2v.x,h2v.y};
            #pragma unroll
            for (int l = 0; l < MN; l++) {
                float Fl = Fbase - ee[l]*invcE - alpha*(hc1 + hh[l]);
                acc += gg[l] * fmaf(m2a, A[l], Fl);
            }
        }
        acc += __shfl_xor_sync(FULLMASK, acc, 16);
        acc += __shfl_xor_sync(FULLMASK, acc, 8);
        acc += __shfl_xor_sync(FULLMASK, acc, 4);
        acc += __shfl_xor_sync(FULLMASK, acc, 2);
        acc += __shfl_xor_sync(FULLMASK, acc, 1);
        if (lane == 0) out[n*T + t] = acc;
    }
}

// ---------------- launch ----------------------------------------------------
extern "C" void kernel_launch(void* const* d_in, const int* in_sizes, int n_in,
                              void* d_out, int out_size) {
    const float* x      = (const float*)d_in[0];
    const int*   edge   = (const int*)  d_in[1];
    const float* tmpl   = (const float*)d_in[2];
    const float* tf     = (const float*)d_in[3];
    const float* q0     = (const float*)d_in[4];
    const float* alpha0 = (const float*)d_in[5];
    const int*   dst    = edge + N_NODES*DEG;
    float* out = (float*)d_out;

    pm_pre_kernel<<<N_NODES/NPB, 512>>>(x, tf, tmpl, q0, alpha0);
    ltfgw_kernel<<<N_NODES, 320>>>(dst, out);
}